// round 1
// baseline (speedup 1.0000x reference)
#include <cuda_runtime.h>
#include <cuda_bf16.h>
#include <cstdint>

#define GH 20      // hidden size
#define GL 5       // layers
#define GT 4096    // timesteps
#define GB 256     // batch

struct GruParams {
    const float* x;          // [B, T, 1]
    const float* Wih[GL];    // [3H, in]
    const float* Whh[GL];    // [3H, H]
    const float* bih[GL];    // [3H]
    const float* bhh[GL];    // [3H]
    const float* Wout;       // [1, L*H]
    const float* bout;       // [1]
    float* out_h;            // [B, T, H]
    float* out_hn;           // [B, L, H]
    float* out_y;            // [B, 1]
};

__device__ __forceinline__ float fast_exp2(float x) {
    float r;
    asm("ex2.approx.f32 %0, %1;" : "=f"(r) : "f"(x));
    return r;
}
__device__ __forceinline__ float fast_rcp(float x) {
    float r;
    asm("rcp.approx.f32 %0, %1;" : "=f"(r) : "f"(x));
    return r;
}
// sigmoid(x) = 1 / (1 + exp(-x)),  exp via ex2.approx (err ~2ulp, no drift risk)
__device__ __forceinline__ float sigmoidf_fast(float x) {
    float e = fast_exp2(-1.4426950408889634f * x);
    return fast_rcp(1.0f + e);
}
// tanh(x) = 2*sigmoid(2x) - 1
__device__ __forceinline__ float tanhf_fast(float x) {
    float e = fast_exp2(-2.8853900817779268f * x);
    float s = fast_rcp(1.0f + e);
    return 2.0f * s - 1.0f;
}

__global__ __launch_bounds__(32 * GL, 2) void gru_wavefront_kernel(GruParams p) {
    __shared__ __align__(16) float hbuf[GL][2][GH];   // double-buffered layer outputs
    __shared__ __align__(16) float hlast[GL * GH];    // final hidden per layer

    const int tid = threadIdx.x;
    const int l   = tid >> 5;     // layer = warp id
    const int i   = tid & 31;     // lane  = hidden unit
    const int b   = blockIdx.x;   // batch element

    // zero the h buffers (h0 = 0)
    for (int q = tid; q < GL * 2 * GH; q += blockDim.x)
        ((float*)hbuf)[q] = 0.0f;

    const bool act = (i < GH);

    // ---- load per-thread weights into registers ----
    float whr[GH], whz[GH], whn[GH];   // W_hh rows i, H+i, 2H+i
    float wxr[GH], wxz[GH], wxn[GH];   // W_ih rows (layers >= 1)
    float br = 0.f, bz = 0.f, bnx = 0.f, bnh = 0.f;
    float w0r = 0.f, w0z = 0.f, w0n = 0.f;

    if (act) {
        const float* Whh = p.Whh[l];
#pragma unroll
        for (int k = 0; k < GH; k++) {
            whr[k] = Whh[(i) * GH + k];
            whz[k] = Whh[(GH + i) * GH + k];
            whn[k] = Whh[(2 * GH + i) * GH + k];
        }
        if (l == 0) {
            const float* Wih = p.Wih[0];
            w0r = Wih[i];
            w0z = Wih[GH + i];
            w0n = Wih[2 * GH + i];
#pragma unroll
            for (int k = 0; k < GH; k++) { wxr[k] = 0.f; wxz[k] = 0.f; wxn[k] = 0.f; }
        } else {
            const float* Wih = p.Wih[l];
#pragma unroll
            for (int k = 0; k < GH; k++) {
                wxr[k] = Wih[(i) * GH + k];
                wxz[k] = Wih[(GH + i) * GH + k];
                wxn[k] = Wih[(2 * GH + i) * GH + k];
            }
        }
        br  = p.bih[l][i]          + p.bhh[l][i];
        bz  = p.bih[l][GH + i]     + p.bhh[l][GH + i];
        bnx = p.bih[l][2 * GH + i];
        bnh = p.bhh[l][2 * GH + i];
    }

    const float* xrow   = p.x     + (size_t)b * GT;       // x[b, :, 0]
    float*       outrow = p.out_h + (size_t)b * GT * GH;  // h[b, :, :]

    __syncthreads();

    // ---- wavefront over global steps: layer l handles t = s - l ----
    for (int s = 0; s < GT + GL - 1; s++) {
        const int t  = s - l;
        const int pw = s & 1;      // write parity
        const int pr = pw ^ 1;     // read parity (written at step s-1)

        if (act && (unsigned)t < (unsigned)GT) {
            // own previous hidden state (full vector, broadcast LDS)
            float hv[GH];
            const float4* hp = (const float4*)hbuf[l][pr];
#pragma unroll
            for (int q = 0; q < GH / 4; q++) {
                float4 v = hp[q];
                hv[4 * q] = v.x; hv[4 * q + 1] = v.y; hv[4 * q + 2] = v.z; hv[4 * q + 3] = v.w;
            }
            const float hown = hv[0] * 0.f + hbuf[l][pr][i];  // scalar read of own unit

            // recurrent dots (3 independent FMA chains)
            float ar = br, az = bz, an = bnh;
#pragma unroll
            for (int k = 0; k < GH; k++) {
                ar += whr[k] * hv[k];
                az += whz[k] * hv[k];
                an += whn[k] * hv[k];
            }

            // input projection
            float xr, xz, xn;
            if (l == 0) {
                const float xt = __ldg(xrow + t);
                xr = w0r * xt;
                xz = w0z * xt;
                xn = bnx + w0n * xt;
            } else {
                float xv[GH];
                const float4* xp = (const float4*)hbuf[l - 1][pr];
#pragma unroll
                for (int q = 0; q < GH / 4; q++) {
                    float4 v = xp[q];
                    xv[4 * q] = v.x; xv[4 * q + 1] = v.y; xv[4 * q + 2] = v.z; xv[4 * q + 3] = v.w;
                }
                xr = 0.f; xz = 0.f; xn = bnx;
#pragma unroll
                for (int k = 0; k < GH; k++) {
                    xr += wxr[k] * xv[k];
                    xz += wxz[k] * xv[k];
                    xn += wxn[k] * xv[k];
                }
            }

            const float r    = sigmoidf_fast(xr + ar);
            const float z    = sigmoidf_fast(xz + az);
            const float n    = tanhf_fast(xn + r * an);
            const float hnew = n + z * (hown - n);     // (1-z)*n + z*h

            hbuf[l][pw][i] = hnew;
            if (l == GL - 1) outrow[(size_t)t * GH + i] = hnew;  // coalesced 80B STG
            if (t == GT - 1) hlast[l * GH + i] = hnew;
        }
        __syncthreads();
    }

    // ---- epilogue: h_n and y_hat ----
    if (tid < GL * GH)
        p.out_hn[(size_t)b * GL * GH + tid] = hlast[tid];

    if (tid < 32) {
        float acc = 0.f;
        for (int j = tid; j < GL * GH; j += 32)
            acc += p.Wout[j] * hlast[j];
#pragma unroll
        for (int off = 16; off; off >>= 1)
            acc += __shfl_xor_sync(0xffffffffu, acc, off);
        if (tid == 0)
            p.out_y[b] = acc + p.bout[0];
    }
}

extern "C" void kernel_launch(void* const* d_in, const int* in_sizes, int n_in,
                              void* d_out, int out_size) {
    (void)in_sizes; (void)n_in; (void)out_size;

    GruParams p;
    p.x = (const float*)d_in[0];
    for (int l = 0; l < GL; l++) {
        p.Wih[l] = (const float*)d_in[1 + 4 * l + 0];
        p.Whh[l] = (const float*)d_in[1 + 4 * l + 1];
        p.bih[l] = (const float*)d_in[1 + 4 * l + 2];
        p.bhh[l] = (const float*)d_in[1 + 4 * l + 3];
    }
    p.Wout = (const float*)d_in[21];
    p.bout = (const float*)d_in[22];

    float* out = (float*)d_out;
    p.out_h  = out;                                   // [B, T, H]
    p.out_hn = out + (size_t)GB * GT * GH;            // [B, L, H]
    p.out_y  = out + (size_t)GB * GT * GH + (size_t)GB * GL * GH;  // [B, 1]

    gru_wavefront_kernel<<<GB, 32 * GL>>>(p);
}

// round 2
// speedup vs baseline: 1.2327x; 1.2327x over previous
#include <cuda_runtime.h>
#include <cuda_bf16.h>
#include <cstdint>

#define GH 20      // hidden size
#define GL 5       // layers
#define GT 4096    // timesteps
#define GB 256     // batch
#define NTHREADS 256   // 8 warps: 4 recurrent + 4 input-projection

using u64 = unsigned long long;

struct GruParams {
    const float* x;          // [B, T, 1]
    const float* Wih[GL];
    const float* Whh[GL];
    const float* bih[GL];
    const float* bhh[GL];
    const float* Wout;       // [1, L*H]
    const float* bout;       // [1]
    float* out_h;            // [B, T, H]
    float* out_hn;           // [B, L, H]
    float* out_y;            // [B, 1]
};

// ---------- packed f32x2 helpers (sm_103a) ----------
__device__ __forceinline__ u64 pack2(float lo, float hi) {
    u64 r; asm("mov.b64 %0, {%1,%2};" : "=l"(r) : "f"(lo), "f"(hi)); return r;
}
__device__ __forceinline__ u64 pks(float w) { return pack2(w, w); }
__device__ __forceinline__ void unpack2(u64 v, float& a, float& b) {
    asm("mov.b64 {%0,%1}, %2;" : "=f"(a), "=f"(b) : "l"(v));
}
__device__ __forceinline__ u64 fma2(u64 a, u64 b, u64 c) {
    u64 d; asm("fma.rn.f32x2 %0, %1, %2, %3;" : "=l"(d) : "l"(a), "l"(b), "l"(c)); return d;
}
__device__ __forceinline__ u64 add2(u64 a, u64 b) {
    u64 d; asm("add.rn.f32x2 %0, %1, %2;" : "=l"(d) : "l"(a), "l"(b)); return d;
}

// ---------- fast activations (ex2/rcp approx, err ~1e-7) ----------
__device__ __forceinline__ float fast_exp2(float x) {
    float r; asm("ex2.approx.f32 %0, %1;" : "=f"(r) : "f"(x)); return r;
}
__device__ __forceinline__ float fast_rcp(float x) {
    float r; asm("rcp.approx.f32 %0, %1;" : "=f"(r) : "f"(x)); return r;
}
__device__ __forceinline__ float sigmoidf_fast(float x) {
    return fast_rcp(1.0f + fast_exp2(-1.4426950408889634f * x));
}
__device__ __forceinline__ float tanhf_fast(float x) {
    float s = fast_rcp(1.0f + fast_exp2(-2.8853900817779268f * x));
    return 2.0f * s - 1.0f;
}

__global__ __launch_bounds__(NTHREADS, 1) void gru_wavefront2_kernel(GruParams p) {
    // batch pair per block, packed (b0, b1) in f32x2 lanes
    __shared__ __align__(16) u64 xs[GT];               // 32 KB: packed x for both batches
    __shared__ __align__(16) u64 hbuf[GL][2][GH];      // double-buffered hidden
    __shared__ __align__(16) u64 xpb[GL][2][3 * GH];   // double-buffered input projections
    __shared__ __align__(16) u64 hlast[GL * GH];

    const int tid  = threadIdx.x;
    const int wid  = tid >> 5;
    const int lane = tid & 31;
    const int b0   = blockIdx.x * 2;
    const int b1   = b0 + 1;

    const float* x0 = p.x + (size_t)b0 * GT;
    const float* x1 = p.x + (size_t)b1 * GT;

    // ---- prologue: stage x into smem (coalesced), zero hidden state ----
    for (int t = tid; t < GT; t += NTHREADS) xs[t] = pack2(x0[t], x1[t]);
    for (int q = tid; q < GL * 2 * GH; q += NTHREADS) ((u64*)hbuf)[q] = 0ull;

    // ---- role / job assignment: homogeneous warps ----
    const bool isRec  = (wid < 4);
    const int  slot   = (wid & 3) * 25 + lane;            // 0..99 within role
    const bool active = (lane < 25) && (slot < GL * GH);
    const int  l = active ? slot / GH : 0;
    const int  i = active ? slot % GH : 0;

    // ---- per-thread weights (packed (w,w)) ----
    u64 w0[GH], w1[GH], w2[GH];
    u64 bias0 = 0, bias1 = 0, bias2 = 0;
    u64 c0r = 0, c0z = 0, c0n = 0;     // layer-0 scalar-input weights (inp role)

    if (active) {
        if (isRec) {
            const float* W = p.Whh[l];
#pragma unroll
            for (int k = 0; k < GH; k++) {
                w0[k] = pks(W[(i) * GH + k]);
                w1[k] = pks(W[(GH + i) * GH + k]);
                w2[k] = pks(W[(2 * GH + i) * GH + k]);
            }
            bias0 = pks(p.bhh[l][i]);
            bias1 = pks(p.bhh[l][GH + i]);
            bias2 = pks(p.bhh[l][2 * GH + i]);
        } else {
            bias0 = pks(p.bih[l][i]);
            bias1 = pks(p.bih[l][GH + i]);
            bias2 = pks(p.bih[l][2 * GH + i]);
            if (l == 0) {
                const float* W = p.Wih[0];
                c0r = pks(W[i]);
                c0z = pks(W[GH + i]);
                c0n = pks(W[2 * GH + i]);
            } else {
                const float* W = p.Wih[l];
#pragma unroll
                for (int k = 0; k < GH; k++) {
                    w0[k] = pks(W[(i) * GH + k]);
                    w1[k] = pks(W[(GH + i) * GH + k]);
                    w2[k] = pks(W[(2 * GH + i) * GH + k]);
                }
            }
        }
    }

    float* outrow0 = p.out_h + (size_t)b0 * GT * GH;
    float* outrow1 = p.out_h + (size_t)b1 * GT * GH;

    __syncthreads();

    // ---- wavefront: rec(l,t) at step s = t + 2l; inp(l) produces xp(l, s+1-2l) ----
    // s = -1 is the priming step (inp(0) computes xp_0(t=0)); last is s = GT-1+2(GL-1).
    for (int s = -1; s < GT + 2 * (GL - 1); s++) {
        const int pw = s & 1;       // write slot
        const int pr = pw ^ 1;      // read slot (written at s-1)

        if (active) {
            if (isRec) {
                const int t = s - 2 * l;
                if ((unsigned)t < (unsigned)GT) {
                    // own previous hidden (packed), vector via LDS.128
                    u64 hv[GH];
                    const ulonglong2* hp = (const ulonglong2*)hbuf[l][pr];
#pragma unroll
                    for (int q = 0; q < GH / 2; q++) {
                        ulonglong2 v = hp[q];
                        hv[2 * q] = v.x; hv[2 * q + 1] = v.y;
                    }
                    const u64 hprev = hbuf[l][pr][i];

                    u64 a0 = bias0, a1 = bias1, a2 = bias2;
#pragma unroll
                    for (int k = 0; k < GH; k++) {
                        a0 = fma2(w0[k], hv[k], a0);
                        a1 = fma2(w1[k], hv[k], a1);
                        a2 = fma2(w2[k], hv[k], a2);
                    }

                    const u64 sr = add2(xpb[l][pr][i],      a0);
                    const u64 sz = add2(xpb[l][pr][GH + i], a1);
                    const u64 xn = xpb[l][pr][2 * GH + i];

                    float srL, srH, szL, szH, anL, anH, xnL, xnH, hL, hH;
                    unpack2(sr, srL, srH);
                    unpack2(sz, szL, szH);
                    unpack2(a2, anL, anH);
                    unpack2(xn, xnL, xnH);
                    unpack2(hprev, hL, hH);

                    const float rL = sigmoidf_fast(srL), rH = sigmoidf_fast(srH);
                    const float zL = sigmoidf_fast(szL), zH = sigmoidf_fast(szH);
                    const float nL = tanhf_fast(fmaf(rL, anL, xnL));
                    const float nH = tanhf_fast(fmaf(rH, anH, xnH));
                    const float hnL = nL + zL * (hL - nL);
                    const float hnH = nH + zH * (hH - nH);

                    const u64 hn = pack2(hnL, hnH);
                    hbuf[l][pw][i] = hn;
                    if (l == GL - 1) {
                        outrow0[(size_t)t * GH + i] = hnL;
                        outrow1[(size_t)t * GH + i] = hnH;
                    }
                    if (t == GT - 1) hlast[l * GH + i] = hn;
                }
            } else {
                const int t = s + 1 - 2 * l;
                if ((unsigned)t < (unsigned)GT) {
                    u64 a0 = bias0, a1 = bias1, a2 = bias2;
                    if (l == 0) {
                        const u64 xt = xs[t];
                        a0 = fma2(c0r, xt, a0);
                        a1 = fma2(c0z, xt, a1);
                        a2 = fma2(c0n, xt, a2);
                    } else {
                        u64 hv[GH];
                        const ulonglong2* hp = (const ulonglong2*)hbuf[l - 1][pr];
#pragma unroll
                        for (int q = 0; q < GH / 2; q++) {
                            ulonglong2 v = hp[q];
                            hv[2 * q] = v.x; hv[2 * q + 1] = v.y;
                        }
#pragma unroll
                        for (int k = 0; k < GH; k++) {
                            a0 = fma2(w0[k], hv[k], a0);
                            a1 = fma2(w1[k], hv[k], a1);
                            a2 = fma2(w2[k], hv[k], a2);
                        }
                    }
                    xpb[l][pw][i]          = a0;
                    xpb[l][pw][GH + i]     = a1;
                    xpb[l][pw][2 * GH + i] = a2;
                }
            }
        }
        __syncthreads();
    }

    // ---- epilogue: h_n and y_hat for both batch elements ----
    if (tid < GL * GH) {
        float a, b;
        unpack2(hlast[tid], a, b);
        p.out_hn[(size_t)b0 * GL * GH + tid] = a;
        p.out_hn[(size_t)b1 * GL * GH + tid] = b;
    }
    if (wid == 0) {
        float aL = 0.f, aH = 0.f;
        for (int j = lane; j < GL * GH; j += 32) {
            const float w = p.Wout[j];
            float xlo, xhi;
            unpack2(hlast[j], xlo, xhi);
            aL = fmaf(w, xlo, aL);
            aH = fmaf(w, xhi, aH);
        }
#pragma unroll
        for (int off = 16; off; off >>= 1) {
            aL += __shfl_xor_sync(0xffffffffu, aL, off);
            aH += __shfl_xor_sync(0xffffffffu, aH, off);
        }
        if (lane == 0) {
            p.out_y[b0] = aL + p.bout[0];
            p.out_y[b1] = aH + p.bout[0];
        }
    }
}

extern "C" void kernel_launch(void* const* d_in, const int* in_sizes, int n_in,
                              void* d_out, int out_size) {
    (void)in_sizes; (void)n_in; (void)out_size;

    GruParams p;
    p.x = (const float*)d_in[0];
    for (int l = 0; l < GL; l++) {
        p.Wih[l] = (const float*)d_in[1 + 4 * l + 0];
        p.Whh[l] = (const float*)d_in[1 + 4 * l + 1];
        p.bih[l] = (const float*)d_in[1 + 4 * l + 2];
        p.bhh[l] = (const float*)d_in[1 + 4 * l + 3];
    }
    p.Wout = (const float*)d_in[21];
    p.bout = (const float*)d_in[22];

    float* out = (float*)d_out;
    p.out_h  = out;
    p.out_hn = out + (size_t)GB * GT * GH;
    p.out_y  = out + (size_t)GB * GT * GH + (size_t)GB * GL * GH;

    gru_wavefront2_kernel<<<GB / 2, NTHREADS>>>(p);
}